// round 1
// baseline (speedup 1.0000x reference)
#include <cuda_runtime.h>
#include <cuda_bf16.h>

// Problem constants
#define B 2
#define H 8
#define T 384
#define S 384
#define D 64
#define BH (B*H)          // 16
#define TT 8              // t-rows per block in main kernel
#define SC 32             // s-chunk width
#define NTILES (BH * (T/TT))  // 768

// Scratch for projected q/k (allocation-free: device globals)
__device__ float g_qp[BH * T * D];   // (bh, t, e)
__device__ float g_kp[BH * S * D];   // (bh, s, e)

__device__ __forceinline__ float tanh_fast(float x) {
    float y;
    asm("tanh.approx.f32 %0, %1;" : "=f"(y) : "f"(x));
    return y;
}

// ---------------------------------------------------------------------------
// Kernel 1: qp = q @ Wq^T, kp = k @ Wk^T   (rows = BH*T = 6144 each)
// ---------------------------------------------------------------------------
__global__ __launch_bounds__(256) void proj_kernel(
    const float* __restrict__ q, const float* __restrict__ k,
    const float* __restrict__ Wq, const float* __restrict__ Wk)
{
    __shared__ float sWq[64][65];
    __shared__ float sWk[64][65];
    __shared__ float sx[4][64];

    for (int i = threadIdx.x; i < 64 * 64; i += 256) {
        int e = i >> 6, d = i & 63;
        sWq[e][d] = Wq[i];
        sWk[e][d] = Wk[i];
    }

    const int NR = BH * T;  // 6144
    const int which = threadIdx.x >> 6;   // 0..3
    const int lane64 = threadIdx.x & 63;  // e index / d index

    for (int r0 = blockIdx.x * 2; r0 < NR; r0 += gridDim.x * 2) {
        __syncthreads();
        // which: 0 -> q row r0, 1 -> k row r0, 2 -> q row r0+1, 3 -> k row r0+1
        const float* src = (which & 1) ? k : q;
        int r = r0 + (which >> 1);
        sx[which][lane64] = src[r * 64 + lane64];
        __syncthreads();

        float acc = 0.0f;
        const float (*W)[65] = (which & 1) ? sWk : sWq;
        #pragma unroll
        for (int dd = 0; dd < 64; ++dd)
            acc = fmaf(sx[which][dd], W[lane64][dd], acc);

        float* dst = (which & 1) ? g_kp : g_qp;
        dst[r * 64 + lane64] = acc;
    }
}

// ---------------------------------------------------------------------------
// Kernel 2: score = v^T tanh(qp + kp), softmax, out = attn @ value
// One block per (bh, t-tile of 8). 256 threads = 8 warps; warp w owns t-row w.
// ---------------------------------------------------------------------------
__global__ __launch_bounds__(256) void attn_kernel(
    const float* __restrict__ value,
    const float* __restrict__ v_w,
    float* __restrict__ out,        // (bh, t, d)
    float* __restrict__ attn_out)   // (bh, t, s)
{
    __shared__ float sh_qp[TT][D + 1];        // 8x65
    __shared__ float sh_vw[D];
    __shared__ float sh_kp[SC][D + 1];        // 32x65
    __shared__ float sh_score[TT][S];         // 8x384
    __shared__ float sh_part[4][TT][D];       // AV partial sums

    const int tile = blockIdx.x;
    const int bh = tile / (T / TT);
    const int t0 = (tile % (T / TT)) * TT;

    const int tid  = threadIdx.x;
    const int warp = tid >> 5;   // = local t
    const int lane = tid & 31;   // = local s within chunk

    // Load qp tile + v_w
    for (int i = tid; i < TT * D; i += 256) {
        int tt = i >> 6, e = i & 63;
        sh_qp[tt][e] = g_qp[(bh * T + t0 + tt) * D + e];
    }
    if (tid < D) sh_vw[tid] = v_w[tid];
    __syncthreads();

    // ---- Score phase: 12 chunks of 32 s-values ----
    for (int sc = 0; sc < S / SC; ++sc) {
        for (int i = tid; i < SC * D; i += 256) {
            int ss = i >> 6, e = i & 63;
            sh_kp[ss][e] = g_kp[(bh * S + sc * SC + ss) * D + e];
        }
        __syncthreads();

        float acc0 = 0.0f, acc1 = 0.0f;
        #pragma unroll
        for (int e = 0; e < D; e += 2) {
            acc0 = fmaf(sh_vw[e],     tanh_fast(sh_qp[warp][e]     + sh_kp[lane][e]),     acc0);
            acc1 = fmaf(sh_vw[e + 1], tanh_fast(sh_qp[warp][e + 1] + sh_kp[lane][e + 1]), acc1);
        }
        sh_score[warp][sc * SC + lane] = acc0 + acc1;
        __syncthreads();
    }

    // ---- Softmax per t-row (warp w handles row w) ----
    {
        const int NPL = S / 32;  // 12 entries per lane
        float vals[NPL];
        float m = -1e30f;
        #pragma unroll
        for (int j = 0; j < NPL; ++j) {
            vals[j] = sh_score[warp][lane + 32 * j];
            m = fmaxf(m, vals[j]);
        }
        #pragma unroll
        for (int off = 16; off > 0; off >>= 1)
            m = fmaxf(m, __shfl_xor_sync(0xFFFFFFFFu, m, off));

        float sum = 0.0f;
        #pragma unroll
        for (int j = 0; j < NPL; ++j) {
            vals[j] = __expf(vals[j] - m);
            sum += vals[j];
        }
        #pragma unroll
        for (int off = 16; off > 0; off >>= 1)
            sum += __shfl_xor_sync(0xFFFFFFFFu, sum, off);

        float inv = __frcp_rn(sum);
        float* arow = attn_out + (size_t)(bh * T + t0 + warp) * S;
        #pragma unroll
        for (int j = 0; j < NPL; ++j) {
            float a = vals[j] * inv;
            sh_score[warp][lane + 32 * j] = a;
            arow[lane + 32 * j] = a;
        }
    }
    __syncthreads();

    // ---- AV epilogue: out[t][d] = sum_s attn[t][s] * value[s][d] ----
    {
        const int d  = tid & 63;
        const int sg = tid >> 6;   // 0..3
        float acc[TT];
        #pragma unroll
        for (int tt = 0; tt < TT; ++tt) acc[tt] = 0.0f;

        for (int s = sg; s < S; s += 4) {
            float v = __ldg(&value[(size_t)(bh * S + s) * D + d]);
            #pragma unroll
            for (int tt = 0; tt < TT; ++tt)
                acc[tt] = fmaf(sh_score[tt][s], v, acc[tt]);
        }
        #pragma unroll
        for (int tt = 0; tt < TT; ++tt) sh_part[sg][tt][d] = acc[tt];
        __syncthreads();

        if (sg == 0) {
            #pragma unroll
            for (int tt = 0; tt < TT; ++tt) {
                float o = sh_part[0][tt][d] + sh_part[1][tt][d]
                        + sh_part[2][tt][d] + sh_part[3][tt][d];
                out[(size_t)(bh * T + t0 + tt) * D + d] = o;
            }
        }
    }
}

// ---------------------------------------------------------------------------
extern "C" void kernel_launch(void* const* d_in, const int* in_sizes, int n_in,
                              void* d_out, int out_size) {
    const float* query = (const float*)d_in[0];
    const float* key   = (const float*)d_in[1];
    const float* value = (const float*)d_in[2];
    const float* Wq    = (const float*)d_in[3];
    const float* Wk    = (const float*)d_in[4];
    const float* v_w   = (const float*)d_in[5];

    float* out_ptr  = (float*)d_out;                    // (b,h,t,d): 393216 floats
    float* attn_ptr = (float*)d_out + (size_t)BH * T * D;  // (b,h,t,s): 2359296 floats

    proj_kernel<<<768, 256>>>(query, key, Wq, Wk);
    attn_kernel<<<NTILES, 256>>>(value, v_w, out_ptr, attn_ptr);
}

// round 4
// speedup vs baseline: 1.0679x; 1.0679x over previous
#include <cuda_runtime.h>
#include <cuda_bf16.h>

#define B 2
#define H 8
#define T 384
#define S 384
#define D 64
#define BH (B*H)            // 16
#define TTB 16              // t-rows per block
#define SC 32               // s-chunk width
#define NBLK (BH * (T/TTB)) // 384

// Scratch for projected q/k (allocation-free: device globals)
__device__ float g_qp[BH * T * D];   // (bh, t, e)
__device__ float g_kp[BH * S * D];   // (bh, s, e)

__device__ __forceinline__ float tanh_fast(float x) {
    float y;
    asm("tanh.approx.f32 %0, %1;" : "=f"(y) : "f"(x));
    return y;
}

// ---------------------------------------------------------------------------
// Kernel 1: qp = q @ Wq^T, kp = k @ Wk^T   (rows = BH*T = 6144 each)
// ---------------------------------------------------------------------------
__global__ __launch_bounds__(256) void proj_kernel(
    const float* __restrict__ q, const float* __restrict__ k,
    const float* __restrict__ Wq, const float* __restrict__ Wk)
{
    __shared__ __align__(16) float sW[2][64][68];   // [q/k][e][d], padded
    __shared__ __align__(16) float sx[4][64];

    for (int i = threadIdx.x; i < 64 * 64; i += 256) {
        int e = i >> 6, d = i & 63;
        sW[0][e][d] = Wq[i];
        sW[1][e][d] = Wk[i];
    }

    const int NR = BH * T;                // 6144
    const int which  = threadIdx.x >> 6;  // 0..3
    const int lane64 = threadIdx.x & 63;  // e index
    const int m = which & 1;              // 0=q, 1=k

    for (int r0 = blockIdx.x * 2; r0 < NR; r0 += gridDim.x * 2) {
        __syncthreads();
        const float* src = m ? k : q;
        int r = r0 + (which >> 1);
        sx[which][lane64] = src[r * 64 + lane64];
        __syncthreads();

        float acc = 0.0f;
        #pragma unroll
        for (int j = 0; j < 16; ++j) {
            float4 w = *(const float4*)&sW[m][lane64][4 * j];
            float4 x = *(const float4*)&sx[which][4 * j];
            acc = fmaf(w.x, x.x, acc);
            acc = fmaf(w.y, x.y, acc);
            acc = fmaf(w.z, x.z, acc);
            acc = fmaf(w.w, x.w, acc);
        }
        float* dst = m ? g_kp : g_qp;
        dst[r * 64 + lane64] = acc;
    }
}

// ---------------------------------------------------------------------------
// Kernel 2: score = v^T tanh(qp + kp), softmax, out = attn @ value
// Block = (bh, 16 t-rows). 8 warps; warp w owns t-rows w and w+8.
// ---------------------------------------------------------------------------
__global__ __launch_bounds__(256) void attn_kernel(
    const float* __restrict__ value,
    const float* __restrict__ v_w,
    float* __restrict__ out,        // (bh, t, d)
    float* __restrict__ attn_out)   // (bh, t, s)
{
    __shared__ __align__(16) float sh_score[TTB][S];  // 24576 B
    __shared__ __align__(16) float sh_u[4096];        // 16384 B (union)

    // Phase-1 view of the union:
    float (*uqp)[68] = (float(*)[68])sh_u;            // 16 rows  -> 1088 floats
    float (*ukp)[68] = (float(*)[68])(sh_u + 1088);   // 32 rows  -> 2176 floats
    float* uvw       = sh_u + 1088 + 2176;            // 64 floats
    // Phase-2 view (AV partials): sh_u as [4][16][64]

    const int tile = blockIdx.x;
    const int bh = tile / (T / TTB);
    const int t0 = (tile % (T / TTB)) * TTB;

    const int tid  = threadIdx.x;
    const int warp = tid >> 5;   // t-rows warp, warp+8
    const int lane = tid & 31;   // s within chunk

    // Stage qp tile (16 rows x 16 float4) + v_w
    {
        int tt = tid >> 4, j = tid & 15;
        *((float4*)&uqp[tt][0] + j) =
            *((const float4*)&g_qp[(bh * T + t0 + tt) * D] + j);
        if (tid < D) uvw[tid] = v_w[tid];
    }
    __syncthreads();

    // Hoist loop-invariant broadcasts into registers (ptxas can't move
    // them across the per-chunk __syncthreads()).
    float4 rvw[16], rq0[16], rq1[16];
    #pragma unroll
    for (int j = 0; j < 16; ++j) {
        rvw[j] = *((const float4*)&uvw[4 * j]);
        rq0[j] = *((const float4*)&uqp[warp][0] + j);
        rq1[j] = *((const float4*)&uqp[warp + 8][0] + j);
    }

    // ---- Score phase: 12 chunks of 32 s-values, 2 t-rows per warp ----
    for (int sc = 0; sc < S / SC; ++sc) {
        #pragma unroll
        for (int kk = 0; kk < 2; ++kk) {
            int i4 = tid + kk * 256;           // 512 float4 total
            int ss = i4 >> 4, j = i4 & 15;
            *((float4*)&ukp[ss][0] + j) =
                *((const float4*)&g_kp[(bh * S + sc * SC + ss) * D] + j);
        }
        __syncthreads();

        float a0 = 0.0f, a1 = 0.0f;
        #pragma unroll
        for (int j = 0; j < 16; ++j) {
            float4 kq = *((const float4*)&ukp[lane][0] + j);
            a0 = fmaf(rvw[j].x, tanh_fast(rq0[j].x + kq.x), a0);
            a1 = fmaf(rvw[j].x, tanh_fast(rq1[j].x + kq.x), a1);
            a0 = fmaf(rvw[j].y, tanh_fast(rq0[j].y + kq.y), a0);
            a1 = fmaf(rvw[j].y, tanh_fast(rq1[j].y + kq.y), a1);
            a0 = fmaf(rvw[j].z, tanh_fast(rq0[j].z + kq.z), a0);
            a1 = fmaf(rvw[j].z, tanh_fast(rq1[j].z + kq.z), a1);
            a0 = fmaf(rvw[j].w, tanh_fast(rq0[j].w + kq.w), a0);
            a1 = fmaf(rvw[j].w, tanh_fast(rq1[j].w + kq.w), a1);
        }
        sh_score[warp][sc * SC + lane]     = a0;
        sh_score[warp + 8][sc * SC + lane] = a1;
        __syncthreads();
    }

    // ---- Softmax: warp handles rows warp and warp+8 ----
    #pragma unroll
    for (int rr0 = 0; rr0 < 2; ++rr0) {
        const int rr = warp + rr0 * 8;
        const int NPL = S / 32;  // 12
        float vals[NPL];
        float m = -1e30f;
        #pragma unroll
        for (int j = 0; j < NPL; ++j) {
            vals[j] = sh_score[rr][lane + 32 * j];
            m = fmaxf(m, vals[j]);
        }
        #pragma unroll
        for (int off = 16; off > 0; off >>= 1)
            m = fmaxf(m, __shfl_xor_sync(0xFFFFFFFFu, m, off));

        float sum = 0.0f;
        #pragma unroll
        for (int j = 0; j < NPL; ++j) {
            vals[j] = __expf(vals[j] - m);
            sum += vals[j];
        }
        #pragma unroll
        for (int off = 16; off > 0; off >>= 1)
            sum += __shfl_xor_sync(0xFFFFFFFFu, sum, off);

        float inv = __frcp_rn(sum);
        float* arow = attn_out + (size_t)(bh * T + t0 + rr) * S;
        #pragma unroll
        for (int j = 0; j < NPL; ++j) {
            float a = vals[j] * inv;
            sh_score[rr][lane + 32 * j] = a;
            arow[lane + 32 * j] = a;
        }
    }
    __syncthreads();   // scores final; qp/kp/vw dead -> union becomes AV partials

    // ---- AV: out[t][d] = sum_s attn[t][s] * value[s][d] ----
    {
        const int d  = tid & 63;
        const int sg = tid >> 6;   // 0..3
        float acc[TTB];
        #pragma unroll
        for (int tt = 0; tt < TTB; ++tt) acc[tt] = 0.0f;

        const float* vbase = value + (size_t)bh * S * D + d;
        for (int s4 = sg * 4; s4 < S; s4 += 16) {
            float v0 = __ldg(vbase + (size_t)(s4 + 0) * D);
            float v1 = __ldg(vbase + (size_t)(s4 + 1) * D);
            float v2 = __ldg(vbase + (size_t)(s4 + 2) * D);
            float v3 = __ldg(vbase + (size_t)(s4 + 3) * D);
            #pragma unroll
            for (int tt = 0; tt < TTB; ++tt) {
                float4 a = *(const float4*)&sh_score[tt][s4];
                float t = fmaf(a.x, v0, fmaf(a.y, v1, fmaf(a.z, v2, a.w * v3)));
                acc[tt] += t;
            }
        }
        #pragma unroll
        for (int tt = 0; tt < TTB; ++tt)
            sh_u[(sg * TTB + tt) * 64 + d] = acc[tt];
        __syncthreads();

        if (sg == 0) {
            #pragma unroll
            for (int tt = 0; tt < TTB; ++tt) {
                float o = sh_u[(0 * TTB + tt) * 64 + d]
                        + sh_u[(1 * TTB + tt) * 64 + d]
                        + sh_u[(2 * TTB + tt) * 64 + d]
                        + sh_u[(3 * TTB + tt) * 64 + d];
                out[(size_t)(bh * T + t0 + tt) * D + d] = o;
            }
        }
    }
}

// ---------------------------------------------------------------------------
extern "C" void kernel_launch(void* const* d_in, const int* in_sizes, int n_in,
                              void* d_out, int out_size) {
    const float* query = (const float*)d_in[0];
    const float* key   = (const float*)d_in[1];
    const float* value = (const float*)d_in[2];
    const float* Wq    = (const float*)d_in[3];
    const float* Wk    = (const float*)d_in[4];
    const float* v_w   = (const float*)d_in[5];

    float* out_ptr  = (float*)d_out;                       // (b,h,t,d)
    float* attn_ptr = (float*)d_out + (size_t)BH * T * D;  // (b,h,t,s)

    proj_kernel<<<768, 256>>>(query, key, Wq, Wk);
    attn_kernel<<<NBLK, 256>>>(value, v_w, out_ptr, attn_ptr);
}

// round 8
// speedup vs baseline: 1.3417x; 1.2564x over previous
#include <cuda_runtime.h>
#include <cuda_bf16.h>

#define B 2
#define H 8
#define T 384
#define S 384
#define D 64
#define BH (B*H)            // 16
#define TTB 16              // t-rows per block
#define SC 32               // s-chunk width
#define NBLK (BH * (T/TTB)) // 384

// Scratch for projected q/k (allocation-free: device globals)
__device__ float g_qp[BH * T * D];   // (bh, t, e)
__device__ float g_kp[BH * S * D];   // (bh, s, e)

__device__ __forceinline__ float tanh_fast(float x) {
    float y;
    asm("tanh.approx.f32 %0, %1;" : "=f"(y) : "f"(x));
    return y;
}

// ---------------------------------------------------------------------------
// Kernel 1: qp = q @ Wq^T, kp = k @ Wk^T   (rows = BH*T = 6144 each)
// ---------------------------------------------------------------------------
__global__ __launch_bounds__(256) void proj_kernel(
    const float* __restrict__ q, const float* __restrict__ k,
    const float* __restrict__ Wq, const float* __restrict__ Wk)
{
    __shared__ __align__(16) float sW[2][64][68];   // [q/k][e][d], padded
    __shared__ __align__(16) float sx[4][64];

    for (int i = threadIdx.x; i < 64 * 64; i += 256) {
        int e = i >> 6, d = i & 63;
        sW[0][e][d] = Wq[i];
        sW[1][e][d] = Wk[i];
    }

    const int NR = BH * T;                // 6144
    const int which  = threadIdx.x >> 6;  // 0..3
    const int lane64 = threadIdx.x & 63;  // e index
    const int m = which & 1;              // 0=q, 1=k

    for (int r0 = blockIdx.x * 2; r0 < NR; r0 += gridDim.x * 2) {
        __syncthreads();
        const float* src = m ? k : q;
        int r = r0 + (which >> 1);
        sx[which][lane64] = src[r * 64 + lane64];
        __syncthreads();

        float acc = 0.0f;
        #pragma unroll
        for (int j = 0; j < 16; ++j) {
            float4 w = *(const float4*)&sW[m][lane64][4 * j];
            float4 x = *(const float4*)&sx[which][4 * j];
            acc = fmaf(w.x, x.x, acc);
            acc = fmaf(w.y, x.y, acc);
            acc = fmaf(w.z, x.z, acc);
            acc = fmaf(w.w, x.w, acc);
        }
        float* dst = m ? g_kp : g_qp;
        dst[r * 64 + lane64] = acc;
    }
}

// ---------------------------------------------------------------------------
// Kernel 2: score = v^T tanh(qp + kp), softmax, out = attn @ value
// Block = (bh, 16 t-rows). 8 warps; warp w owns t-rows w and w+8.
// __launch_bounds__(256, 4): cap regs at 64 so 4 blocks/SM stay resident.
// ---------------------------------------------------------------------------
__global__ __launch_bounds__(256, 4) void attn_kernel(
    const float* __restrict__ value,
    const float* __restrict__ v_w,
    float* __restrict__ out,        // (bh, t, d)
    float* __restrict__ attn_out)   // (bh, t, s)
{
    __shared__ __align__(16) float sh_score[TTB][S];  // 24576 B
    __shared__ __align__(16) float sh_u[4096];        // 16384 B (union)

    // Phase-1 view of the union:
    float (*uqp)[68] = (float(*)[68])sh_u;            // 16 rows  -> 1088 floats
    float (*ukp)[68] = (float(*)[68])(sh_u + 1088);   // 32 rows  -> 2176 floats
    float* uvw       = sh_u + 1088 + 2176;            // 64 floats
    // Phase-2 view (AV partials): sh_u as [4][16][64]

    const int tile = blockIdx.x;
    const int bh = tile / (T / TTB);
    const int t0 = (tile % (T / TTB)) * TTB;

    const int tid  = threadIdx.x;
    const int warp = tid >> 5;   // t-rows warp, warp+8
    const int lane = tid & 31;   // s within chunk

    // Stage qp tile (16 rows x 16 float4) + v_w
    {
        int tt = tid >> 4, j = tid & 15;
        *((float4*)&uqp[tt][0] + j) =
            *((const float4*)&g_qp[(bh * T + t0 + tt) * D] + j);
        if (tid < D) uvw[tid] = v_w[tid];
    }
    __syncthreads();

    // ---- Score phase: 12 chunks of 32 s-values, 2 t-rows per warp ----
    // vw/q0/q1 are BROADCAST smem reads (cheap wavefronts); only kq is per-lane.
    for (int sc = 0; sc < S / SC; ++sc) {
        #pragma unroll
        for (int kk = 0; kk < 2; ++kk) {
            int i4 = tid + kk * 256;           // 512 float4 total
            int ss = i4 >> 4, j = i4 & 15;
            *((float4*)&ukp[ss][0] + j) =
                *((const float4*)&g_kp[(bh * S + sc * SC + ss) * D] + j);
        }
        __syncthreads();

        float a0 = 0.0f, a1 = 0.0f;
        #pragma unroll
        for (int j = 0; j < 16; ++j) {
            float4 kq = *((const float4*)&ukp[lane][0] + j);
            float4 wv = *((const float4*)&uvw[4 * j]);
            float4 q0 = *((const float4*)&uqp[warp][0] + j);
            float4 q1 = *((const float4*)&uqp[warp + 8][0] + j);
            a0 = fmaf(wv.x, tanh_fast(q0.x + kq.x), a0);
            a1 = fmaf(wv.x, tanh_fast(q1.x + kq.x), a1);
            a0 = fmaf(wv.y, tanh_fast(q0.y + kq.y), a0);
            a1 = fmaf(wv.y, tanh_fast(q1.y + kq.y), a1);
            a0 = fmaf(wv.z, tanh_fast(q0.z + kq.z), a0);
            a1 = fmaf(wv.z, tanh_fast(q1.z + kq.z), a1);
            a0 = fmaf(wv.w, tanh_fast(q0.w + kq.w), a0);
            a1 = fmaf(wv.w, tanh_fast(q1.w + kq.w), a1);
        }
        sh_score[warp][sc * SC + lane]     = a0;
        sh_score[warp + 8][sc * SC + lane] = a1;
        __syncthreads();
    }

    // ---- Softmax: warp handles rows warp and warp+8 ----
    #pragma unroll
    for (int rr0 = 0; rr0 < 2; ++rr0) {
        const int rr = warp + rr0 * 8;
        const int NPL = S / 32;  // 12
        float vals[NPL];
        float m = -1e30f;
        #pragma unroll
        for (int j = 0; j < NPL; ++j) {
            vals[j] = sh_score[rr][lane + 32 * j];
            m = fmaxf(m, vals[j]);
        }
        #pragma unroll
        for (int off = 16; off > 0; off >>= 1)
            m = fmaxf(m, __shfl_xor_sync(0xFFFFFFFFu, m, off));

        float sum = 0.0f;
        #pragma unroll
        for (int j = 0; j < NPL; ++j) {
            vals[j] = __expf(vals[j] - m);
            sum += vals[j];
        }
        #pragma unroll
        for (int off = 16; off > 0; off >>= 1)
            sum += __shfl_xor_sync(0xFFFFFFFFu, sum, off);

        float inv = __frcp_rn(sum);
        float* arow = attn_out + (size_t)(bh * T + t0 + rr) * S;
        #pragma unroll
        for (int j = 0; j < NPL; ++j) {
            float a = vals[j] * inv;
            sh_score[rr][lane + 32 * j] = a;
            arow[lane + 32 * j] = a;
        }
    }
    __syncthreads();   // scores final; qp/kp/vw dead -> union becomes AV partials

    // ---- AV: out[t][d] = sum_s attn[t][s] * value[s][d] ----
    {
        const int d  = tid & 63;
        const int sg = tid >> 6;   // 0..3
        float acc[TTB];
        #pragma unroll
        for (int tt = 0; tt < TTB; ++tt) acc[tt] = 0.0f;

        const float* vbase = value + (size_t)bh * S * D + d;
        for (int s4 = sg * 4; s4 < S; s4 += 16) {
            float v0 = __ldg(vbase + (size_t)(s4 + 0) * D);
            float v1 = __ldg(vbase + (size_t)(s4 + 1) * D);
            float v2 = __ldg(vbase + (size_t)(s4 + 2) * D);
            float v3 = __ldg(vbase + (size_t)(s4 + 3) * D);
            #pragma unroll
            for (int tt = 0; tt < TTB; ++tt) {
                float4 a = *(const float4*)&sh_score[tt][s4];
                float t = fmaf(a.x, v0, fmaf(a.y, v1, fmaf(a.z, v2, a.w * v3)));
                acc[tt] += t;
            }
        }
        #pragma unroll
        for (int tt = 0; tt < TTB; ++tt)
            sh_u[(sg * TTB + tt) * 64 + d] = acc[tt];
        __syncthreads();

        if (sg == 0) {
            #pragma unroll
            for (int tt = 0; tt < TTB; ++tt) {
                float o = sh_u[(0 * TTB + tt) * 64 + d]
                        + sh_u[(1 * TTB + tt) * 64 + d]
                        + sh_u[(2 * TTB + tt) * 64 + d]
                        + sh_u[(3 * TTB + tt) * 64 + d];
                out[(size_t)(bh * T + t0 + tt) * D + d] = o;
            }
        }
    }
}

// ---------------------------------------------------------------------------
extern "C" void kernel_launch(void* const* d_in, const int* in_sizes, int n_in,
                              void* d_out, int out_size) {
    const float* query = (const float*)d_in[0];
    const float* key   = (const float*)d_in[1];
    const float* value = (const float*)d_in[2];
    const float* Wq    = (const float*)d_in[3];
    const float* Wk    = (const float*)d_in[4];
    const float* v_w   = (const float*)d_in[5];

    float* out_ptr  = (float*)d_out;                       // (b,h,t,d)
    float* attn_ptr = (float*)d_out + (size_t)BH * T * D;  // (b,h,t,s)

    proj_kernel<<<256, 256>>>(query, key, Wq, Wk);
    attn_kernel<<<NBLK, 256>>>(value, v_w, out_ptr, attn_ptr);
}